// round 7
// baseline (speedup 1.0000x reference)
#include <cuda_runtime.h>
#include <math.h>
#include <stdint.h>

#define BB 8
#define CC 512
#define CQ 64
#define NN 4096   // H*W

typedef unsigned long long u64;

// ---------------- packed fp32x2 helpers ----------------
__device__ __forceinline__ u64 pack2(float lo, float hi) {
    u64 r; asm("mov.b64 %0, {%1, %2};" : "=l"(r) : "f"(lo), "f"(hi)); return r;
}
__device__ __forceinline__ void unpack2(u64 v, float& lo, float& hi) {
    asm("mov.b64 {%0, %1}, %2;" : "=f"(lo), "=f"(hi) : "l"(v));
}
__device__ __forceinline__ u64 ffma2(u64 a, u64 b, u64 c) {
    u64 d; asm("fma.rn.f32x2 %0, %1, %2, %3;" : "=l"(d) : "l"(a), "l"(b), "l"(c)); return d;
}
__device__ __forceinline__ u64 fmul2(u64 a, u64 b) {
    u64 d; asm("mul.rn.f32x2 %0, %1, %2;" : "=l"(d) : "l"(a), "l"(b)); return d;
}

// ---------------- cp.async helpers ----------------
__device__ __forceinline__ uint32_t smem_u32(const void* p) {
    uint32_t a;
    asm("{ .reg .u64 t; cvta.to.shared.u64 t, %1; cvt.u32.u64 %0, t; }" : "=r"(a) : "l"(p));
    return a;
}
__device__ __forceinline__ void cp16(uint32_t s, const void* g) {
    asm volatile("cp.async.cg.shared.global [%0], [%1], 16;" :: "r"(s), "l"(g));
}
#define CP_COMMIT()  asm volatile("cp.async.commit_group;" ::: "memory")
#define CP_WAIT(n)   asm volatile("cp.async.wait_group %0;" :: "n"(n) : "memory")

// ---------------- scratch (80 MB — the footprint that passes) ----------------
__device__ float d_f[(size_t)BB * CQ * NN];          // fT: (b, d, i)  8 MB
__device__ float d_g[(size_t)BB * CQ * NN];          // gT: (b, d, j)  8 MB
__device__ float d_h[(size_t)BB * NN * CC];          // h : (b, i, c) 64 MB
__device__ float d_rsig[3];

// ---------------- 1) spectral sigma ----------------
__global__ void sigma_kernel(const float* __restrict__ Wf, const float* __restrict__ Wg,
                             const float* __restrict__ Wh, const float* __restrict__ uf,
                             const float* __restrict__ ug, const float* __restrict__ uh) {
    const int w = blockIdx.x;
    const float* W; const float* u; int M;
    if (w == 0)      { W = Wf; u = uf; M = CQ; }
    else if (w == 1) { W = Wg; u = ug; M = CQ; }
    else             { W = Wh; u = uh; M = CC; }
    const int K = CC;

    __shared__ float t[CC];
    __shared__ float red[CC];
    __shared__ float wsum[16];
    __shared__ float vnorm;
    const int tid = threadIdx.x;
    const int lane = tid & 31, warp = tid >> 5;

    float acc = 0.f;
#pragma unroll 8
    for (int m = 0; m < M; m++) acc += W[m * K + tid] * u[m];
    t[tid] = acc;
    red[tid] = acc * acc;
    __syncthreads();
    for (int s = 256; s > 0; s >>= 1) { if (tid < s) red[tid] += red[tid + s]; __syncthreads(); }
    if (tid == 0) vnorm = sqrtf(red[0]) + 1e-12f;
    __syncthreads();
    t[tid] *= (1.f / vnorm);
    __syncthreads();

    float local = 0.f;
    for (int m = warp; m < M; m += 16) {
        const float* Wr = W + (size_t)m * K;
        float a = 0.f;
#pragma unroll 4
        for (int k = lane; k < K; k += 32) a += Wr[k] * t[k];
#pragma unroll
        for (int o = 16; o > 0; o >>= 1) a += __shfl_xor_sync(0xFFFFFFFFu, a, o);
        local += a * a;
    }
    if (lane == 0) wsum[warp] = local;
    __syncthreads();
    if (tid == 0) {
        float nw2 = 0.f;
#pragma unroll
        for (int i = 0; i < 16; i++) nw2 += wsum[i];
        float nw = sqrtf(nw2);
        d_rsig[w] = (nw + 1e-12f) / nw2;   // 1/sigma
    }
}

// ---------------- 2) fused projections; f,g stored transposed (b,d,n) ----------------
__global__ void __launch_bounds__(256) proj_kernel(
    const float* __restrict__ x,
    const float* __restrict__ Wf, const float* __restrict__ bf,
    const float* __restrict__ Wg, const float* __restrict__ bg,
    const float* __restrict__ Wh, const float* __restrict__ bh) {
    const int K = CC;
    const int n0 = blockIdx.x * 64;
    const int o0 = blockIdx.y * 64;
    const int b  = blockIdx.z;

    const float* W; const float* bias; int seg, orow0;
    if (o0 < 64)       { seg = 0; W = Wf; bias = bf; orow0 = o0; }
    else if (o0 < 128) { seg = 1; W = Wg; bias = bg; orow0 = o0 - 64; }
    else               { seg = 2; W = Wh; bias = bh; orow0 = o0 - 128; }

    __shared__ float Ws[32][69];
    __shared__ float xs[32][68];

    const int tid = threadIdx.y * 16 + threadIdx.x;
    const int tx = threadIdx.x, ty = threadIdx.y;

    u64 accp[4][2];
#pragma unroll
    for (int i = 0; i < 4; i++) { accp[i][0] = 0ull; accp[i][1] = 0ull; }

    const size_t xbase = (size_t)b * CC * NN;

    for (int kc = 0; kc < K; kc += 32) {
#pragma unroll
        for (int r = 0; r < 8; r++) {
            int e = tid + 256 * r;
            int kk = e >> 6, nn = e & 63;
            xs[kk][nn] = x[xbase + (size_t)(kc + kk) * NN + n0 + nn];
        }
#pragma unroll
        for (int r = 0; r < 8; r++) {
            int e = tid + 256 * r;
            int kk = e & 31, oo = e >> 5;
            Ws[kk][oo] = W[(size_t)(orow0 + oo) * K + kc + kk];
        }
        __syncthreads();
#pragma unroll
        for (int kk = 0; kk < 32; kk++) {
            ulonglong2 bv = *(const ulonglong2*)&xs[kk][tx * 4];
#pragma unroll
            for (int i = 0; i < 4; i++) {
                float a = Ws[kk][ty * 4 + i];
                u64 A = pack2(a, a);
                accp[i][0] = ffma2(A, bv.x, accp[i][0]);
                accp[i][1] = ffma2(A, bv.y, accp[i][1]);
            }
        }
        __syncthreads();
    }

    const float rs = d_rsig[seg];
    const u64 rs2 = pack2(rs, rs);
#pragma unroll
    for (int i = 0; i < 4; i++) {
        const int orow = orow0 + ty * 4 + i;
        const float bia = bias[orow];
        const u64 b2 = pack2(bia, bia);
        u64 r0 = ffma2(accp[i][0], rs2, b2);
        u64 r1 = ffma2(accp[i][1], rs2, b2);
        if (seg < 2) {
            float* dst = (seg == 0 ? d_f : d_g) + ((size_t)b * CQ + orow) * NN + n0 + tx * 4;
            *(u64*)dst = r0;
            *(u64*)(dst + 2) = r1;
        } else {
            float v[4];
            unpack2(r0, v[0], v[1]);
            unpack2(r1, v[2], v[3]);
#pragma unroll
            for (int j = 0; j < 4; j++)
                d_h[((size_t)b * NN + n0 + tx * 4 + j) * CC + orow] = v[j];
        }
    }
}

// ---------------- 3) tiled flash attention, 512 threads --------------------------
// Block: 128 queries (j), 256 channels (c-half), batch b. 16 warps (4/SMSP).
// Thread: 8 j (4 packed j-pairs, jloc = 2*ty + 32*mj, ty = warp) x 8 c (c = lane + 32*q).
// Key tiles of 32 double-buffered via cp.async.
//
// smem (float offsets):
#define GS_OFF   0        // gs[64][128]            32 KB
#define HS0_OFF  8192     // hs buf0 [32][256]      32 KB
#define HS1_OFF  16384    // hs buf1
#define FS0_OFF  24576    // fs buf0 [64][32]        8 KB
#define FS1_OFF  26624    // fs buf1
#define PS_OFF   28672    // Ps[32][130]            16.6 KB
#define SMEM_FLOATS 32832 // 131328 bytes

extern __shared__ float sm_attn[];

__global__ void __launch_bounds__(512, 1) attn_kernel(
    const float* __restrict__ x, const float* __restrict__ gamma,
    float* __restrict__ out) {
    const int b  = blockIdx.z;
    const int c0 = blockIdx.y * 256;
    const int j0 = blockIdx.x * 128;
    const int tid = threadIdx.x;
    const int lane = tid & 31, ty = tid >> 5;   // ty = warp id (0..15)
    const int jloc = 2 * ty;                    // + 32*mj

    const float* gT = d_g + (size_t)b * CQ * NN;
    const float* fT = d_f + (size_t)b * CQ * NN;
    const float* hb = d_h + (size_t)b * NN * CC;

    float* gs = sm_attn + GS_OFF;
    float* Ps = sm_attn + PS_OFF;

    // resident g tile: gs[d][j]  (64 x 128 = 2048 float4, 4 per thread)
#pragma unroll
    for (int r = 0; r < 4; r++) {
        int e = tid + 512 * r;
        int d = e >> 5, jc = (e & 31) * 4;
        *(float4*)&gs[d * 128 + jc] = *(const float4*)&gT[(size_t)d * NN + j0 + jc];
    }

    u64 acc[4][8];                              // [mj][q]: (j, j+1) x c = lane + 32q
#pragma unroll
    for (int mj = 0; mj < 4; mj++)
#pragma unroll
        for (int q = 0; q < 8; q++) acc[mj][q] = 0ull;
    float mrow[8], lrow[8];
#pragma unroll
    for (int r = 0; r < 8; r++) { mrow[r] = -INFINITY; lrow[r] = 0.f; }

    // prefetch tile 0
    {
        float* fsb = sm_attn + FS0_OFF;
        float* hsb = sm_attn + HS0_OFF;
        {   // fs: 512 float4, 1 per thread
            int d = tid >> 3, ic = (tid & 7) * 4;
            cp16(smem_u32(&fsb[d * 32 + ic]), &fT[(size_t)d * NN + ic]);
        }
#pragma unroll
        for (int r = 0; r < 4; r++) {           // hs: 2048 float4
            int e = tid + 512 * r;
            int i = e >> 6, cc = (e & 63) * 4;
            cp16(smem_u32(&hsb[i * 256 + cc]), &hb[(size_t)i * CC + c0 + cc]);
        }
        CP_COMMIT();
    }
    __syncthreads();                            // gs visible

    for (int t = 0; t < 128; t++) {
        const int buf = t & 1;
        if (t + 1 < 128) {                      // prefetch next tile
            float* fsb = sm_attn + (buf ? FS0_OFF : FS1_OFF);
            float* hsb = sm_attn + (buf ? HS0_OFF : HS1_OFF);
            const int i0 = (t + 1) * 32;
            {
                int d = tid >> 3, ic = (tid & 7) * 4;
                cp16(smem_u32(&fsb[d * 32 + ic]), &fT[(size_t)d * NN + i0 + ic]);
            }
#pragma unroll
            for (int r = 0; r < 4; r++) {
                int e = tid + 512 * r;
                int i = e >> 6, cc = (e & 63) * 4;
                cp16(smem_u32(&hsb[i * 256 + cc]), &hb[(size_t)(i0 + i) * CC + c0 + cc]);
            }
            CP_COMMIT();
            CP_WAIT(1);                         // tile t complete
        } else {
            CP_WAIT(0);
        }
        __syncthreads();

        const float* fsb = sm_attn + (buf ? FS1_OFF : FS0_OFF);
        const float* hsb = sm_attn + (buf ? HS1_OFF : HS0_OFF);

        // --- S phase: sa[mj] = (S[j][i], S[j+1][i]), i = lane ---
        u64 sa[4] = {0ull, 0ull, 0ull, 0ull};
#pragma unroll 8
        for (int d = 0; d < 64; d++) {
            float fv = fsb[d * 32 + lane];
            u64 F = pack2(fv, fv);
#pragma unroll
            for (int mj = 0; mj < 4; mj++) {
                u64 ga = *(const u64*)&gs[d * 128 + jloc + 32 * mj];
                sa[mj] = ffma2(ga, F, sa[mj]);
            }
        }

        // --- online softmax (reduce over the 32 lanes = keys), Ps store, rescale ---
#pragma unroll
        for (int mj = 0; mj < 4; mj++) {
            float sA, sB;
            unpack2(sa[mj], sA, sB);            // rows j, j+1 at key i = lane
            // row A
            float tmA = sA;
#pragma unroll
            for (int o = 16; o > 0; o >>= 1) tmA = fmaxf(tmA, __shfl_xor_sync(0xFFFFFFFFu, tmA, o));
            float mA = fmaxf(mrow[2 * mj], tmA);
            float scA = __expf(mrow[2 * mj] - mA);
            float pA = __expf(sA - mA);
            float suA = pA;
#pragma unroll
            for (int o = 16; o > 0; o >>= 1) suA += __shfl_xor_sync(0xFFFFFFFFu, suA, o);
            lrow[2 * mj] = lrow[2 * mj] * scA + suA;
            mrow[2 * mj] = mA;
            // row B
            float tmB = sB;
#pragma unroll
            for (int o = 16; o > 0; o >>= 1) tmB = fmaxf(tmB, __shfl_xor_sync(0xFFFFFFFFu, tmB, o));
            float mB = fmaxf(mrow[2 * mj + 1], tmB);
            float scB = __expf(mrow[2 * mj + 1] - mB);
            float pB = __expf(sB - mB);
            float suB = pB;
#pragma unroll
            for (int o = 16; o > 0; o >>= 1) suB += __shfl_xor_sync(0xFFFFFFFFu, suB, o);
            lrow[2 * mj + 1] = lrow[2 * mj + 1] * scB + suB;
            mrow[2 * mj + 1] = mB;

            // Ps[i = lane][j-pair]  (producer warp == consumer warp)
            *(u64*)&Ps[lane * 130 + jloc + 32 * mj] = pack2(pA, pB);

            const u64 scp = pack2(scA, scB);
#pragma unroll
            for (int q = 0; q < 8; q++) acc[mj][q] = fmul2(acc[mj][q], scp);
        }
        __syncwarp();

        // --- PV phase: acc[mj][q] += P[j-pair][k] * h[k][c] ---
        const float* Pr = Ps + jloc;
#pragma unroll 4
        for (int k = 0; k < 32; k++) {
            u64 pa[4];
            const float* Prk = Pr + k * 130;
#pragma unroll
            for (int mj = 0; mj < 4; mj++)
                pa[mj] = *(const u64*)&Prk[32 * mj];
            const float* hr = &hsb[k * 256 + lane];
#pragma unroll
            for (int q = 0; q < 8; q++) {
                float hv = hr[32 * q];
                u64 H = pack2(hv, hv);
#pragma unroll
                for (int mj = 0; mj < 4; mj++)
                    acc[mj][q] = ffma2(pa[mj], H, acc[mj][q]);
            }
        }
        __syncthreads();                        // before buffers are refilled
    }

    // --- epilogue: y[b,c,(j,j+1)] = gamma * acc / l + x ---
    const float gam = gamma[0];
    const u64 G = pack2(gam, gam);
    u64 rl[4];
#pragma unroll
    for (int mj = 0; mj < 4; mj++)
        rl[mj] = pack2(1.f / lrow[2 * mj], 1.f / lrow[2 * mj + 1]);
    const size_t xb = (size_t)b * CC * NN;
#pragma unroll
    for (int q = 0; q < 8; q++) {
        const int c = c0 + lane + 32 * q;
        const size_t base = xb + (size_t)c * NN + j0 + jloc;
#pragma unroll
        for (int mj = 0; mj < 4; mj++) {
            const size_t idx = base + 32 * mj;
            u64 xv = *(const u64*)&x[idx];
            u64 t2 = fmul2(acc[mj][q], rl[mj]);
            *(u64*)&out[idx] = ffma2(t2, G, xv);
        }
    }
}

// ---------------- launch ----------------
extern "C" void kernel_launch(void* const* d_in, const int* in_sizes, int n_in,
                              void* d_out, int out_size) {
    (void)in_sizes; (void)n_in; (void)out_size;
    const float* x     = (const float*)d_in[0];
    const float* Wf    = (const float*)d_in[1];
    const float* bf    = (const float*)d_in[2];
    const float* Wg    = (const float*)d_in[3];
    const float* bg    = (const float*)d_in[4];
    const float* Wh    = (const float*)d_in[5];
    const float* bh    = (const float*)d_in[6];
    const float* gamma = (const float*)d_in[7];
    const float* uf    = (const float*)d_in[8];
    const float* ug    = (const float*)d_in[9];
    const float* uh    = (const float*)d_in[10];
    float* out = (float*)d_out;

    cudaFuncSetAttribute(attn_kernel, cudaFuncAttributeMaxDynamicSharedMemorySize,
                         SMEM_FLOATS * (int)sizeof(float));

    sigma_kernel<<<3, 512>>>(Wf, Wg, Wh, uf, ug, uh);
    proj_kernel<<<dim3(NN / 64, 10, BB), dim3(16, 16)>>>(x, Wf, bf, Wg, bg, Wh, bh);
    attn_kernel<<<dim3(NN / 128, 2, BB), 512, SMEM_FLOATS * sizeof(float)>>>(x, gamma, out);
}

// round 9
// speedup vs baseline: 1.9626x; 1.9626x over previous
#include <cuda_runtime.h>
#include <cuda_bf16.h>
#include <math.h>
#include <stdint.h>

#define BB 8
#define CC 512
#define CQ 64
#define NN 4096   // H*W

typedef unsigned long long u64;
typedef unsigned int u32;

// ---------------- packed fp32x2 helpers ----------------
__device__ __forceinline__ u64 pack2(float lo, float hi) {
    u64 r; asm("mov.b64 %0, {%1, %2};" : "=l"(r) : "f"(lo), "f"(hi)); return r;
}
__device__ __forceinline__ void unpack2(u64 v, float& lo, float& hi) {
    asm("mov.b64 {%0, %1}, %2;" : "=f"(lo), "=f"(hi) : "l"(v));
}
__device__ __forceinline__ u64 ffma2(u64 a, u64 b, u64 c) {
    u64 d; asm("fma.rn.f32x2 %0, %1, %2, %3;" : "=l"(d) : "l"(a), "l"(b), "l"(c)); return d;
}

// bf16 pair pack: element order in memory = (lo_elem, hi_elem)
__device__ __forceinline__ u32 bf2(float lo, float hi) {
    u32 r; asm("cvt.rn.bf16x2.f32 %0, %1, %2;" : "=r"(r) : "f"(hi), "f"(lo)); return r;
}
__device__ __forceinline__ float bfround(float x) {
    return __bfloat162float(__float2bfloat16_rn(x));
}

// ---------------- cp.async helpers ----------------
__device__ __forceinline__ u32 smem_u32(const void* p) {
    u32 a;
    asm("{ .reg .u64 t; cvta.to.shared.u64 t, %1; cvt.u32.u64 %0, t; }" : "=r"(a) : "l"(p));
    return a;
}
__device__ __forceinline__ void cp16(u32 s, const void* g) {
    asm volatile("cp.async.cg.shared.global [%0], [%1], 16;" :: "r"(s), "l"(g));
}
#define CP_COMMIT()  asm volatile("cp.async.commit_group;" ::: "memory")
#define CP_WAIT(n)   asm volatile("cp.async.wait_group %0;" :: "n"(n) : "memory")

// ---------------- warp mma.sync bf16 (baseline PTX, works on sm_100) ----------------
__device__ __forceinline__ void mma_bf16(float* c, const u32* a, u32 b0, u32 b1) {
    asm volatile(
        "mma.sync.aligned.m16n8k16.row.col.f32.bf16.bf16.f32 "
        "{%0,%1,%2,%3}, {%4,%5,%6,%7}, {%8,%9}, {%0,%1,%2,%3};"
        : "+f"(c[0]), "+f"(c[1]), "+f"(c[2]), "+f"(c[3])
        : "r"(a[0]), "r"(a[1]), "r"(a[2]), "r"(a[3]), "r"(b0), "r"(b1));
}

// ---------------- scratch (176 MB) ----------------
__device__ float d_f[(size_t)BB * CQ * NN];               // fT: (b, d, i)   8 MB
__device__ float d_g[(size_t)BB * CQ * NN];               // gT: (b, d, j)   8 MB
__device__ __nv_bfloat16 d_hThi[(size_t)BB * CC * NN];    // hT hi (b,c,i)  16 MB
__device__ __nv_bfloat16 d_hTlo[(size_t)BB * CC * NN];    // hT lo          16 MB
__device__ float d_S[(size_t)NN * NN];                    // S (one batch)  64 MB
__device__ __nv_bfloat16 d_Phi[(size_t)NN * NN];          // P hi (1 batch) 32 MB
__device__ __nv_bfloat16 d_Plo[(size_t)NN * NN];          // P lo           32 MB
__device__ float d_rsig[3];

// ---------------- 1) spectral sigma ----------------
__global__ void sigma_kernel(const float* __restrict__ Wf, const float* __restrict__ Wg,
                             const float* __restrict__ Wh, const float* __restrict__ uf,
                             const float* __restrict__ ug, const float* __restrict__ uh) {
    const int w = blockIdx.x;
    const float* W; const float* u; int M;
    if (w == 0)      { W = Wf; u = uf; M = CQ; }
    else if (w == 1) { W = Wg; u = ug; M = CQ; }
    else             { W = Wh; u = uh; M = CC; }
    const int K = CC;

    __shared__ float t[CC];
    __shared__ float red[CC];
    __shared__ float wsum[16];
    __shared__ float vnorm;
    const int tid = threadIdx.x;
    const int lane = tid & 31, warp = tid >> 5;

    float acc = 0.f;
#pragma unroll 8
    for (int m = 0; m < M; m++) acc += W[m * K + tid] * u[m];
    t[tid] = acc;
    red[tid] = acc * acc;
    __syncthreads();
    for (int s = 256; s > 0; s >>= 1) { if (tid < s) red[tid] += red[tid + s]; __syncthreads(); }
    if (tid == 0) vnorm = sqrtf(red[0]) + 1e-12f;
    __syncthreads();
    t[tid] *= (1.f / vnorm);
    __syncthreads();

    float local = 0.f;
    for (int m = warp; m < M; m += 16) {
        const float* Wr = W + (size_t)m * K;
        float a = 0.f;
#pragma unroll 4
        for (int k = lane; k < K; k += 32) a += Wr[k] * t[k];
#pragma unroll
        for (int o = 16; o > 0; o >>= 1) a += __shfl_xor_sync(0xFFFFFFFFu, a, o);
        local += a * a;
    }
    if (lane == 0) wsum[warp] = local;
    __syncthreads();
    if (tid == 0) {
        float nw2 = 0.f;
#pragma unroll
        for (int i = 0; i < 16; i++) nw2 += wsum[i];
        float nw = sqrtf(nw2);
        d_rsig[w] = (nw + 1e-12f) / nw2;   // 1/sigma
    }
}

// ---------------- 2) projections; f,g fp32 transposed; hT bf16 hi/lo ----------------
__global__ void __launch_bounds__(256) proj_kernel(
    const float* __restrict__ x,
    const float* __restrict__ Wf, const float* __restrict__ bf,
    const float* __restrict__ Wg, const float* __restrict__ bg,
    const float* __restrict__ Wh, const float* __restrict__ bh) {
    const int K = CC;
    const int n0 = blockIdx.x * 64;
    const int o0 = blockIdx.y * 64;
    const int b  = blockIdx.z;

    const float* W; const float* bias; int seg, orow0;
    if (o0 < 64)       { seg = 0; W = Wf; bias = bf; orow0 = o0; }
    else if (o0 < 128) { seg = 1; W = Wg; bias = bg; orow0 = o0 - 64; }
    else               { seg = 2; W = Wh; bias = bh; orow0 = o0 - 128; }

    __shared__ float Ws[32][69];
    __shared__ float xs[32][68];

    const int tid = threadIdx.y * 16 + threadIdx.x;
    const int tx = threadIdx.x, ty = threadIdx.y;

    u64 accp[4][2];
#pragma unroll
    for (int i = 0; i < 4; i++) { accp[i][0] = 0ull; accp[i][1] = 0ull; }

    const size_t xbase = (size_t)b * CC * NN;

    for (int kc = 0; kc < K; kc += 32) {
#pragma unroll
        for (int r = 0; r < 8; r++) {
            int e = tid + 256 * r;
            int kk = e >> 6, nn = e & 63;
            xs[kk][nn] = x[xbase + (size_t)(kc + kk) * NN + n0 + nn];
        }
#pragma unroll
        for (int r = 0; r < 8; r++) {
            int e = tid + 256 * r;
            int kk = e & 31, oo = e >> 5;
            Ws[kk][oo] = W[(size_t)(orow0 + oo) * K + kc + kk];
        }
        __syncthreads();
#pragma unroll
        for (int kk = 0; kk < 32; kk++) {
            ulonglong2 bv = *(const ulonglong2*)&xs[kk][tx * 4];
#pragma unroll
            for (int i = 0; i < 4; i++) {
                float a = Ws[kk][ty * 4 + i];
                u64 A = pack2(a, a);
                accp[i][0] = ffma2(A, bv.x, accp[i][0]);
                accp[i][1] = ffma2(A, bv.y, accp[i][1]);
            }
        }
        __syncthreads();
    }

    const float rs = d_rsig[seg];
    const u64 rs2 = pack2(rs, rs);
#pragma unroll
    for (int i = 0; i < 4; i++) {
        const int orow = orow0 + ty * 4 + i;
        const float bia = bias[orow];
        const u64 b2 = pack2(bia, bia);
        u64 r0 = ffma2(accp[i][0], rs2, b2);
        u64 r1 = ffma2(accp[i][1], rs2, b2);
        if (seg < 2) {
            float* dst = (seg == 0 ? d_f : d_g) + ((size_t)b * CQ + orow) * NN + n0 + tx * 4;
            *(u64*)dst = r0;
            *(u64*)(dst + 2) = r1;
        } else {
            float v[4];
            unpack2(r0, v[0], v[1]);
            unpack2(r1, v[2], v[3]);
            float hi[4], lo[4];
#pragma unroll
            for (int j = 0; j < 4; j++) { hi[j] = bfround(v[j]); lo[j] = v[j] - hi[j]; }
            const size_t base = ((size_t)b * CC + orow) * NN + n0 + tx * 4;
            uint2 ph; ph.x = bf2(hi[0], hi[1]); ph.y = bf2(hi[2], hi[3]);
            uint2 pl; pl.x = bf2(lo[0], lo[1]); pl.y = bf2(lo[2], lo[3]);
            *(uint2*)&d_hThi[base] = ph;
            *(uint2*)&d_hTlo[base] = pl;
        }
    }
}

// ---------------- 3) S = g^T f : S[j,i] for batch b, fp32 SIMT ----------------
__global__ void __launch_bounds__(256, 2) s_kernel(int b) {
    const int j0 = blockIdx.x * 128;
    const int i0 = blockIdx.y * 128;
    __shared__ float As[32][128];      // [k(d)][m(j)]
    __shared__ float Bs[32][128];      // [k(d)][n(i)]

    const int tid = threadIdx.x;
    const int tx = tid & 15, ty = tid >> 4;

    u64 acc[8][4];
#pragma unroll
    for (int im = 0; im < 8; im++)
#pragma unroll
        for (int nq = 0; nq < 4; nq++) acc[im][nq] = 0ull;

    const float* gT = d_g + (size_t)b * CQ * NN;
    const float* fT = d_f + (size_t)b * CQ * NN;

    for (int k0 = 0; k0 < CQ; k0 += 32) {
        {
            const int kw = tid >> 5;
            const int m4 = tid & 31;
#pragma unroll
            for (int r = 0; r < 4; r++) {
                int k = kw + 8 * r;
                *(float4*)&As[k][m4 * 4] = *(const float4*)&gT[(size_t)(k0 + k) * NN + j0 + m4 * 4];
                *(float4*)&Bs[k][m4 * 4] = *(const float4*)&fT[(size_t)(k0 + k) * NN + i0 + m4 * 4];
            }
        }
        __syncthreads();
#pragma unroll
        for (int k = 0; k < 32; k++) {
            u64 bp[4];
#pragma unroll
            for (int nq = 0; nq < 4; nq++) bp[nq] = *(const u64*)&Bs[k][2 * tx + 32 * nq];
#pragma unroll
            for (int im = 0; im < 8; im++) {
                float a = As[k][ty + 16 * im];
                u64 asp = pack2(a, a);
#pragma unroll
                for (int nq = 0; nq < 4; nq++)
                    acc[im][nq] = ffma2(asp, bp[nq], acc[im][nq]);
            }
        }
        __syncthreads();
    }

#pragma unroll
    for (int im = 0; im < 8; im++) {
        float* rowp = d_S + (size_t)(j0 + ty + 16 * im) * NN + i0;
#pragma unroll
        for (int nq = 0; nq < 4; nq++)
            *(u64*)&rowp[2 * tx + 32 * nq] = acc[im][nq];
    }
}

// ---------------- 4) row softmax over i; emit P as bf16 hi/lo ----------------
__global__ void __launch_bounds__(256) softmax_kernel() {
    const int j = blockIdx.x;
    const float* row = d_S + (size_t)j * NN;
    const int tid = threadIdx.x;
    const int lane = tid & 31, warp = tid >> 5;
    __shared__ float red[8];
    __shared__ float bcast;

    float4 v[4];
#pragma unroll
    for (int r = 0; r < 4; r++) v[r] = *(const float4*)&row[(tid + 256 * r) * 4];

    float m = -INFINITY;
#pragma unroll
    for (int r = 0; r < 4; r++)
        m = fmaxf(m, fmaxf(fmaxf(v[r].x, v[r].y), fmaxf(v[r].z, v[r].w)));
#pragma unroll
    for (int o = 16; o > 0; o >>= 1) m = fmaxf(m, __shfl_xor_sync(0xFFFFFFFFu, m, o));
    if (lane == 0) red[warp] = m;
    __syncthreads();
    if (tid == 0) {
        float mm = red[0];
#pragma unroll
        for (int i = 1; i < 8; i++) mm = fmaxf(mm, red[i]);
        bcast = mm;
    }
    __syncthreads();
    const float M = bcast;

    float s = 0.f;
#pragma unroll
    for (int r = 0; r < 4; r++) {
        v[r].x = __expf(v[r].x - M); v[r].y = __expf(v[r].y - M);
        v[r].z = __expf(v[r].z - M); v[r].w = __expf(v[r].w - M);
        s += v[r].x + v[r].y + v[r].z + v[r].w;
    }
#pragma unroll
    for (int o = 16; o > 0; o >>= 1) s += __shfl_xor_sync(0xFFFFFFFFu, s, o);
    if (lane == 0) red[warp] = s;
    __syncthreads();
    if (tid == 0) {
        float ss = 0.f;
#pragma unroll
        for (int i = 0; i < 8; i++) ss += red[i];
        bcast = 1.f / ss;
    }
    __syncthreads();
    const float inv = bcast;
    const size_t ro = (size_t)j * NN;
#pragma unroll
    for (int r = 0; r < 4; r++) {
        float p0 = v[r].x * inv, p1 = v[r].y * inv, p2 = v[r].z * inv, p3 = v[r].w * inv;
        float h0 = bfround(p0), h1 = bfround(p1), h2 = bfround(p2), h3 = bfround(p3);
        uint2 ph; ph.x = bf2(h0, h1); ph.y = bf2(h2, h3);
        uint2 pl; pl.x = bf2(p0 - h0, p1 - h1); pl.y = bf2(p2 - h2, p3 - h3);
        const size_t idx = ro + (size_t)(tid + 256 * r) * 4;
        *(uint2*)&d_Phi[idx] = ph;
        *(uint2*)&d_Plo[idx] = pl;
    }
}

// ---------------- 5) PV via mma.sync bf16 (3-term split) ----------------
// CTA: 128 j x 128 c. 8 warps: warp = (wm 0..3)x(wn 0..1) -> 32j x 64c subtile.
// K = 4096 (i) in chunks of 32, double-buffered cp.async.
// Fragment maps (m16n8k16.row.col): A row-major [m][k] (P[j][i]); B col-major
// k x n == memory [n][k] with k contiguous (hT[c][i]). Both load as LDS.32.
#define TSTRIDE 40                    // padded row stride in bf16 (conflict-free)
#define TILE_BF (128 * TSTRIDE)       // 5120 bf16 per tile
#define STAGE_BF (4 * TILE_BF)        // Ahi, Alo, Bhi, Blo
#define PV_SMEM (2 * STAGE_BF * 2)    // bytes = 81920

extern __shared__ __nv_bfloat16 pv_sm[];

__device__ __forceinline__ void pv_load_stage(
    __nv_bfloat16* st, const __nv_bfloat16* Hhi, const __nv_bfloat16* Hlo,
    int j0, int c0, int kc, int tid) {
    const u32 sb = smem_u32(st);
#pragma unroll
    for (int r = 0; r < 2; r++) {                 // A tiles: P rows (j)
        int e = tid + 256 * r;
        int row = e >> 2, c16 = e & 3;
        const size_t src = (size_t)(j0 + row) * NN + kc + c16 * 8;
        u32 dst = sb + row * (TSTRIDE * 2) + c16 * 16;
        cp16(dst, &d_Phi[src]);
        cp16(dst + TILE_BF * 2, &d_Plo[src]);
    }
#pragma unroll
    for (int r = 0; r < 2; r++) {                 // B tiles: hT rows (c)
        int e = tid + 256 * r;
        int row = e >> 2, c16 = e & 3;
        const size_t src = (size_t)(c0 + row) * NN + kc + c16 * 8;
        u32 dst = sb + 2 * (TILE_BF * 2) + row * (TSTRIDE * 2) + c16 * 16;
        cp16(dst, &Hhi[src]);
        cp16(dst + TILE_BF * 2, &Hlo[src]);
    }
    CP_COMMIT();
}

__global__ void __launch_bounds__(256, 2) pv_kernel(
    int b, const float* __restrict__ x, const float* __restrict__ gamma,
    float* __restrict__ out) {
    const int j0 = blockIdx.x * 128;
    const int c0 = blockIdx.y * 128;
    const int tid = threadIdx.x;
    const int lane = tid & 31, wid = tid >> 5;
    const int g = lane >> 2, t4 = lane & 3;       // fragment coords
    const int jw = (wid >> 1) * 32;               // warp j offset
    const int cw = (wid & 1) * 64;                // warp c offset

    const __nv_bfloat16* Hhi = d_hThi + (size_t)b * CC * NN;
    const __nv_bfloat16* Hlo = d_hTlo + (size_t)b * CC * NN;

    float acc[2][8][4];
#pragma unroll
    for (int mi = 0; mi < 2; mi++)
#pragma unroll
        for (int ni = 0; ni < 8; ni++)
#pragma unroll
            for (int q = 0; q < 4; q++) acc[mi][ni][q] = 0.f;

    pv_load_stage(pv_sm, Hhi, Hlo, j0, c0, 0, tid);

    for (int tch = 0; tch < 128; tch++) {
        if (tch + 1 < 128) {
            pv_load_stage(pv_sm + ((tch + 1) & 1) * STAGE_BF, Hhi, Hlo,
                          j0, c0, (tch + 1) * 32, tid);
            CP_WAIT(1);
        } else {
            CP_WAIT(0);
        }
        __syncthreads();

        const __nv_bfloat16* st = pv_sm + (tch & 1) * STAGE_BF;
        const __nv_bfloat16* sAhi = st;
        const __nv_bfloat16* sAlo = st + TILE_BF;
        const __nv_bfloat16* sBhi = st + 2 * TILE_BF;
        const __nv_bfloat16* sBlo = st + 3 * TILE_BF;

#pragma unroll
        for (int s = 0; s < 2; s++) {
            const int kb = s * 16;
            u32 ahi[2][4], alo[2][4];
#pragma unroll
            for (int mi = 0; mi < 2; mi++) {
                const int r0 = jw + mi * 16 + g;
                const int cA = kb + 2 * t4;
                ahi[mi][0] = *(const u32*)&sAhi[r0 * TSTRIDE + cA];
                ahi[mi][1] = *(const u32*)&sAhi[(r0 + 8) * TSTRIDE + cA];
                ahi[mi][2] = *(const u32*)&sAhi[r0 * TSTRIDE + cA + 8];
                ahi[mi][3] = *(const u32*)&sAhi[(r0 + 8) * TSTRIDE + cA + 8];
                alo[mi][0] = *(const u32*)&sAlo[r0 * TSTRIDE + cA];
                alo[mi][1] = *(const u32*)&sAlo[(r0 + 8) * TSTRIDE + cA];
                alo[mi][2] = *(const u32*)&sAlo[r0 * TSTRIDE + cA + 8];
                alo[mi][3] = *(const u32*)&sAlo[(r0 + 8) * TSTRIDE + cA + 8];
            }
#pragma unroll
            for (int ni = 0; ni < 8; ni++) {
                const int nr = cw + ni * 8 + g;
                const int cB = kb + 2 * t4;
                u32 bh0 = *(const u32*)&sBhi[nr * TSTRIDE + cB];
                u32 bh1 = *(const u32*)&sBhi[nr * TSTRIDE + cB + 8];
                u32 bl0 = *(const u32*)&sBlo[nr * TSTRIDE + cB];
                u32 bl1 = *(const u32*)&sBlo[nr * TSTRIDE + cB + 8];
#pragma unroll
                for (int mi = 0; mi < 2; mi++) {
                    mma_bf16(acc[mi][ni], ahi[mi], bh0, bh1);   // hi*hi
                    mma_bf16(acc[mi][ni], ahi[mi], bl0, bl1);   // hi*lo
                    mma_bf16(acc[mi][ni], alo[mi], bh0, bh1);   // lo*hi
                }
            }
        }
        __syncthreads();
    }

    // epilogue: y[b,c,j] = gamma * o + x. D frag: c0:(m=g,n=2t) c1:(g,2t+1) c2:(g+8,2t) c3:(g+8,2t+1)
    const float gam = gamma[0];
    const size_t xb = (size_t)b * CC * NN;
#pragma unroll
    for (int mi = 0; mi < 2; mi++) {
        const int m0 = j0 + jw + mi * 16 + g;
#pragma unroll
        for (int ni = 0; ni < 8; ni++) {
            const int n0 = c0 + cw + ni * 8 + 2 * t4;
            const size_t i00 = xb + (size_t)n0 * NN + m0;        // (c=n0,   j=m0)
            const size_t i01 = i00 + NN;                          // (c=n0+1, j=m0)
            out[i00]     = gam * acc[mi][ni][0] + x[i00];
            out[i01]     = gam * acc[mi][ni][1] + x[i01];
            out[i00 + 8] = gam * acc[mi][ni][2] + x[i00 + 8];     // j=m0+8
            out[i01 + 8] = gam * acc[mi][ni][3] + x[i01 + 8];
        }
    }
}

// ---------------- launch ----------------
extern "C" void kernel_launch(void* const* d_in, const int* in_sizes, int n_in,
                              void* d_out, int out_size) {
    (void)in_sizes; (void)n_in; (void)out_size;
    const float* x     = (const float*)d_in[0];
    const float* Wf    = (const float*)d_in[1];
    const float* bf    = (const float*)d_in[2];
    const float* Wg    = (const float*)d_in[3];
    const float* bg    = (const float*)d_in[4];
    const float* Wh    = (const float*)d_in[5];
    const float* bh    = (const float*)d_in[6];
    const float* gamma = (const float*)d_in[7];
    const float* uf    = (const float*)d_in[8];
    const float* ug    = (const float*)d_in[9];
    const float* uh    = (const float*)d_in[10];
    float* out = (float*)d_out;

    cudaFuncSetAttribute(pv_kernel, cudaFuncAttributeMaxDynamicSharedMemorySize, PV_SMEM);

    sigma_kernel<<<3, 512>>>(Wf, Wg, Wh, uf, ug, uh);
    proj_kernel<<<dim3(NN / 64, 10, BB), dim3(16, 16)>>>(x, Wf, bf, Wg, bg, Wh, bh);
    for (int b = 0; b < BB; b++) {
        s_kernel<<<dim3(NN / 128, NN / 128), 256>>>(b);
        softmax_kernel<<<NN, 256>>>();
        pv_kernel<<<dim3(NN / 128, CC / 128), 256, PV_SMEM>>>(b, x, gamma, out);
    }
}